// round 5
// baseline (speedup 1.0000x reference)
#include <cuda_runtime.h>
#include <cuda_fp16.h>
#include <cstdint>
#include <math.h>

// ---------------- problem constants ----------------
#define KDIM 768
#define HSZ  1024
#define BM   128          // rows per CTA
#define BN   128          // W cols per h-tile pass
#define KC   64           // K elems per stage (64 fp16 = 128B row = SW128 atom)
#define KSTAGES 12        // 768/64
#define NHT  8            // 1024/128
#define MAXB 65536
#define NTHREADS 256

// ---------------- smem layout ----------------
#define OFF_L1T 0          // l1_w transposed [2048][8] f32 = 65536 B
#define OFF_FTB 65536      // ft_b 1024 f32 = 4096 B
#define OFF_STG 69632      // 2 stages x (Aw 16K + Ab 16K + W 16K) = 98304 B
#define STG_BYTES 49152
#define SMEM_TOTAL (OFF_STG + 2 * STG_BYTES)   // 167936

#define SW128(o) ((o) ^ (((o) >> 3) & 0x70))

// ---------------- PTX helpers ----------------
__device__ __forceinline__ uint32_t smem_u32(const void* p) {
    uint32_t a;
    asm("{ .reg .u64 t; cvta.to.shared.u64 t, %1; cvt.u32.u64 %0, t; }" : "=r"(a) : "l"(p));
    return a;
}

#define LDSM4(R, addr) \
    asm volatile("ldmatrix.sync.aligned.m8n8.x4.shared.b16 {%0,%1,%2,%3}, [%4];" \
        : "=r"((R)[0]), "=r"((R)[1]), "=r"((R)[2]), "=r"((R)[3]) : "r"(addr))

#define MMA(D, A, B0, B1) \
    asm volatile("mma.sync.aligned.m16n8k16.row.col.f32.f16.f16.f32 " \
        "{%0,%1,%2,%3}, {%4,%5,%6,%7}, {%8,%9}, {%0,%1,%2,%3};" \
        : "+f"((D)[0]), "+f"((D)[1]), "+f"((D)[2]), "+f"((D)[3]) \
        : "r"((A)[0]), "r"((A)[1]), "r"((A)[2]), "r"((A)[3]), "r"(B0), "r"(B1))

#define CP_ASYNC16(dst, src) \
    asm volatile("cp.async.cg.shared.global [%0], [%1], 16;" :: "r"(dst), "l"(src) : "memory")
#define CP_COMMIT  asm volatile("cp.async.commit_group;" ::: "memory")
#define CP_WAIT(N) asm volatile("cp.async.wait_group %0;" :: "n"(N) : "memory")

// ---------------- fp16 scratch (device globals: allocation is forbidden) ----------------
__device__ __half g_wbf[(size_t)MAXB * KDIM];
__device__ __half g_bbf[(size_t)MAXB * KDIM];
__device__ __half g_ftwbf[(size_t)HSZ * KDIM];

// ---------------- fp32 -> fp16 convert ----------------
__global__ void cvt_fp16_kernel(const float* __restrict__ src,
                                __half* __restrict__ dst, int n4) {
    int i = blockIdx.x * blockDim.x + threadIdx.x;
    if (i < n4) {
        float4 v = ((const float4*)src)[i];
        union { __half2 h2[2]; uint2 u; } pk;
        pk.h2[0] = __floats2half2_rn(v.x, v.y);
        pk.h2[1] = __floats2half2_rn(v.z, v.w);
        ((uint2*)dst)[i] = pk.u;
    }
}

// ---------------- stage loader: 3 tiles of 128 rows x 64 fp16, SW128 swizzle ----------------
__device__ __forceinline__ void load_stage(uint32_t dst, const __half* aw,
                                           const __half* ab, const __half* wt,
                                           int k0, int tid) {
    #pragma unroll
    for (int it = 0; it < 4; ++it) {
        const int ch = tid + it * NTHREADS;        // 0..1023 chunks of 16B
        const int rr = ch >> 3, cc = ch & 7;
        const uint32_t so = SW128(rr * 128 + cc * 16);
        const size_t go = (size_t)rr * KDIM + k0 + cc * 8;
        CP_ASYNC16(dst + so,          aw + go);
        CP_ASYNC16(dst + 16384 + so,  ab + go);
        CP_ASYNC16(dst + 32768 + so,  wt + go);
    }
}

// l1 partial accumulation for one column (8 outputs), vectorized l1 weights
#define ACCP(P, A1, A2) do { \
    (P)[0] = fmaf(la0.x, (A1), fmaf(lb0.x, (A2), (P)[0])); \
    (P)[1] = fmaf(la0.y, (A1), fmaf(lb0.y, (A2), (P)[1])); \
    (P)[2] = fmaf(la0.z, (A1), fmaf(lb0.z, (A2), (P)[2])); \
    (P)[3] = fmaf(la0.w, (A1), fmaf(lb0.w, (A2), (P)[3])); \
    (P)[4] = fmaf(la1.x, (A1), fmaf(lb1.x, (A2), (P)[4])); \
    (P)[5] = fmaf(la1.y, (A1), fmaf(lb1.y, (A2), (P)[5])); \
    (P)[6] = fmaf(la1.z, (A1), fmaf(lb1.z, (A2), (P)[6])); \
    (P)[7] = fmaf(la1.w, (A1), fmaf(lb1.w, (A2), (P)[7])); \
} while (0)

// ---------------- fused NNUE kernel ----------------
__global__ __launch_bounds__(NTHREADS) void nnue_main(
    const __half* __restrict__ Aw, const __half* __restrict__ Ab,
    const __half* __restrict__ Wt,
    const float* __restrict__ stm, const float* __restrict__ ft_b,
    const float* __restrict__ l1_w, const float* __restrict__ l1_b,
    const float* __restrict__ l2_w, const float* __restrict__ l2_b,
    const float* __restrict__ l3_w, const float* __restrict__ l3_b,
    float* __restrict__ out, int B, int out_size)
{
    extern __shared__ char smem[];
    const int tid = threadIdx.x;
    const int wid = tid >> 5, lid = tid & 31;
    const int wr = wid >> 1;   // 0..3 : 32-row band
    const int wc = wid & 1;    // 0..1 : 64-col band
    const uint32_t sb = smem_u32(smem);

    float* l1t   = (float*)(smem + OFF_L1T);   // [hc][i] transposed l1_w
    float* ftb_s = (float*)(smem + OFF_FTB);

    // preload l1_w transposed + ft_b (coalesced global reads)
    for (int idx = tid; idx < 2 * HSZ * 8; idx += NTHREADS) {
        const int i = idx >> 11;        // 0..7
        const int hc = idx & 2047;      // 0..2047
        l1t[hc * 8 + i] = l1_w[idx];    // idx == i*2048 + hc
    }
    for (int idx = tid; idx < HSZ; idx += NTHREADS) ftb_s[idx] = ft_b[idx];

    const int row0 = blockIdx.x * BM;

    // rows owned by this thread's accumulator fragments (4 row-pairs halves)
    // p[k] : k = mt*2 + half, row = wr*32 + mt*16 + half*8 + lid/4
    float s_[4], iv_[4];
    #pragma unroll
    for (int k = 0; k < 4; ++k) {
        const int rl = wr * 32 + (k >> 1) * 16 + (k & 1) * 8 + (lid >> 2);
        s_[k] = stm[row0 + rl];
        iv_[k] = 1.0f - s_[k];
    }

    float p[4][8];
    #pragma unroll
    for (int k = 0; k < 4; ++k)
        #pragma unroll
        for (int i = 0; i < 8; ++i) p[k][i] = 0.0f;

    // per-lane ldmatrix geometry
    const int a_kb  = (lid >> 4) << 4;                          // A: 0 or 16 bytes
    const int a_rb  = (wr * 32 + (lid & 15)) * 128;             // A row byte base (mt0)
    const int b_row = wc * 64 + (lid & 7) + ((lid >> 4) << 3);  // B: n row
    const int b_kb  = ((lid >> 3) & 1) << 4;                    // B: 0 or 16 bytes

    const __half* Awr = Aw + (size_t)row0 * KDIM;
    const __half* Abr = Ab + (size_t)row0 * KDIM;

    __syncthreads();

    for (int ht = 0; ht < NHT; ++ht) {
        float accW[64], accB[64];   // [mt*32 + nt*4 + e]
        #pragma unroll
        for (int i = 0; i < 64; ++i) { accW[i] = 0.0f; accB[i] = 0.0f; }

        const __half* Wh = Wt + (size_t)(ht * BN) * KDIM;

        load_stage(sb + OFF_STG, Awr, Abr, Wh, 0, tid);
        CP_COMMIT;

        for (int ks = 0; ks < KSTAGES; ++ks) {
            if (ks < KSTAGES - 1) {
                load_stage(sb + OFF_STG + ((ks + 1) & 1) * STG_BYTES,
                           Awr, Abr, Wh, (ks + 1) * KC, tid);
                CP_COMMIT;
                CP_WAIT(1);
            } else {
                CP_WAIT(0);
            }
            __syncthreads();

            const uint32_t base = sb + OFF_STG + (ks & 1) * STG_BYTES;
            const uint32_t awb = base, abb = base + 16384, wbb = base + 32768;

            #pragma unroll
            for (int kk = 0; kk < 4; ++kk) {
                const int kb = kk * 32;
                uint32_t aw0[4], aw1[4], ab0[4], ab1[4];
                LDSM4(aw0, awb + SW128(a_rb + kb + a_kb));
                LDSM4(aw1, awb + SW128(a_rb + 16 * 128 + kb + a_kb));
                LDSM4(ab0, abb + SW128(a_rb + kb + a_kb));
                LDSM4(ab1, abb + SW128(a_rb + 16 * 128 + kb + a_kb));
                #pragma unroll
                for (int bt = 0; bt < 4; ++bt) {
                    uint32_t bb[4];
                    LDSM4(bb, wbb + SW128((b_row + bt * 16) * 128 + kb + b_kb));
                    MMA(&accW[(bt * 2)     * 4], aw0, bb[0], bb[1]);
                    MMA(&accW[(bt * 2 + 1) * 4], aw0, bb[2], bb[3]);
                    MMA(&accW[32 + (bt * 2)     * 4], aw1, bb[0], bb[1]);
                    MMA(&accW[32 + (bt * 2 + 1) * 4], aw1, bb[2], bb[3]);
                    MMA(&accB[(bt * 2)     * 4], ab0, bb[0], bb[1]);
                    MMA(&accB[(bt * 2 + 1) * 4], ab0, bb[2], bb[3]);
                    MMA(&accB[32 + (bt * 2)     * 4], ab1, bb[0], bb[1]);
                    MMA(&accB[32 + (bt * 2 + 1) * 4], ab1, bb[2], bb[3]);
                }
            }
            __syncthreads();
        }

        // ---- epilogue: ft_b add, stm mix, clip, l1 partial accumulation ----
        #pragma unroll
        for (int mt = 0; mt < 2; ++mt) {
            const float sA = s_[mt * 2],     ivA = iv_[mt * 2];
            const float sB = s_[mt * 2 + 1], ivB = iv_[mt * 2 + 1];
            #pragma unroll
            for (int nt = 0; nt < 8; ++nt) {
                #pragma unroll
                for (int j = 0; j < 2; ++j) {
                    const int hc = ht * BN + wc * 64 + nt * 8 + (lid & 3) * 2 + j;
                    const float fb = ftb_s[hc];
                    const float wvA = accW[mt * 32 + nt * 4 + j] + fb;
                    const float bvA = accB[mt * 32 + nt * 4 + j] + fb;
                    const float wvB = accW[mt * 32 + nt * 4 + 2 + j] + fb;
                    const float bvB = accB[mt * 32 + nt * 4 + 2 + j] + fb;
                    const float a1A = __saturatef(sA * wvA + ivA * bvA);
                    const float a2A = __saturatef(sA * bvA + ivA * wvA);
                    const float a1B = __saturatef(sB * wvB + ivB * bvB);
                    const float a2B = __saturatef(sB * bvB + ivB * wvB);
                    const float4 la0 = *(const float4*)(l1t + hc * 8);
                    const float4 la1 = *(const float4*)(l1t + hc * 8 + 4);
                    const float4 lb0 = *(const float4*)(l1t + (HSZ + hc) * 8);
                    const float4 lb1 = *(const float4*)(l1t + (HSZ + hc) * 8 + 4);
                    ACCP(p[mt * 2],     a1A, a2A);
                    ACCP(p[mt * 2 + 1], a1B, a2B);
                }
            }
        }
    }

    // ---- reduce l1 partials across lane%4 quads, then across the 2 warp-cols ----
    #pragma unroll
    for (int k = 0; k < 4; ++k)
        #pragma unroll
        for (int i = 0; i < 8; ++i) {
            p[k][i] += __shfl_xor_sync(0xffffffffu, p[k][i], 1);
            p[k][i] += __shfl_xor_sync(0xffffffffu, p[k][i], 2);
        }

    __syncthreads();
    float* red = (float*)(smem + OFF_STG);   // 128 x 8 f32, reuses stage area
    if (wc == 1 && (lid & 3) == 0) {
        #pragma unroll
        for (int k = 0; k < 4; ++k) {
            const int rl = wr * 32 + (k >> 1) * 16 + (k & 1) * 8 + (lid >> 2);
            #pragma unroll
            for (int i = 0; i < 8; ++i) red[rl * 8 + i] = p[k][i];
        }
    }
    __syncthreads();
    if (wc == 0 && (lid & 3) == 0) {
        #pragma unroll
        for (int k = 0; k < 4; ++k) {
            const int rl = wr * 32 + (k >> 1) * 16 + (k & 1) * 8 + (lid >> 2);
            float x1[8];
            #pragma unroll
            for (int i = 0; i < 8; ++i)
                x1[i] = __saturatef(p[k][i] + red[rl * 8 + i] + l1_b[i]);
            float raw = l3_b[0];
            #pragma unroll
            for (int j = 0; j < 32; ++j) {
                float s2 = l2_b[j];
                #pragma unroll
                for (int i = 0; i < 8; ++i) s2 = fmaf(l2_w[j * 8 + i], x1[i], s2);
                s2 = __saturatef(s2);
                raw = fmaf(l3_w[j], s2, raw);
            }
            const int grow = row0 + rl;
            out[grow] = 1.0f / (1.0f + expf(-raw));
            if (out_size >= 2 * B) out[B + grow] = raw;
        }
    }
}

// ---------------- launch ----------------
extern "C" void kernel_launch(void* const* d_in, const int* in_sizes, int n_in,
                              void* d_out, int out_size) {
    const float* wf  = (const float*)d_in[0];
    const float* bf  = (const float*)d_in[1];
    const float* stm = (const float*)d_in[2];
    const float* ftw = (const float*)d_in[3];
    const float* ftb = (const float*)d_in[4];
    const float* l1w = (const float*)d_in[5];
    const float* l1b = (const float*)d_in[6];
    const float* l2w = (const float*)d_in[7];
    const float* l2b = (const float*)d_in[8];
    const float* l3w = (const float*)d_in[9];
    const float* l3b = (const float*)d_in[10];

    const int B = in_sizes[0] / KDIM;

    __half *pw = nullptr, *pb = nullptr, *pf = nullptr;
    cudaGetSymbolAddress((void**)&pw, g_wbf);
    cudaGetSymbolAddress((void**)&pb, g_bbf);
    cudaGetSymbolAddress((void**)&pf, g_ftwbf);

    cudaFuncSetAttribute(nnue_main, cudaFuncAttributeMaxDynamicSharedMemorySize, SMEM_TOTAL);

    const int n4 = B * KDIM / 4;
    cvt_fp16_kernel<<<(n4 + 255) / 256, 256>>>(wf, pw, n4);
    cvt_fp16_kernel<<<(n4 + 255) / 256, 256>>>(bf, pb, n4);
    const int n4w = HSZ * KDIM / 4;
    cvt_fp16_kernel<<<(n4w + 255) / 256, 256>>>(ftw, pf, n4w);

    nnue_main<<<B / BM, NTHREADS, SMEM_TOTAL>>>(pw, pb, pf, stm, ftb,
                                                l1w, l1b, l2w, l2b, l3w, l3b,
                                                (float*)d_out, B, out_size);
}

// round 7
// speedup vs baseline: 1.0109x; 1.0109x over previous
#include <cuda_runtime.h>
#include <cuda_fp16.h>
#include <cstdint>
#include <math.h>

// ---------------- problem constants ----------------
#define KDIM 768
#define HSZ  1024
#define BM   128          // rows per CTA
#define BN   128          // W cols per h-tile pass
#define KC   64           // K elems per stage (64 fp16 = 128B row = SW128 atom)
#define KSTAGES 12        // 768/64
#define NHT  8            // 1024/128
#define MAXB 65536
#define NTHREADS 256
#define NBUF 3            // cp.async pipeline depth

// ---------------- smem layout ----------------
#define OFF_L1T 0          // l1_w transposed [2048][8] f32 = 65536 B
#define OFF_FTB 65536      // ft_b 1024 f32 = 4096 B
#define OFF_STG 69632      // 3 stages x (Aw 16K + Ab 16K + W 16K) = 147456 B
#define STG_BYTES 49152
#define SMEM_TOTAL (OFF_STG + NBUF * STG_BYTES)   // 217088

#define SW128(o) ((o) ^ (((o) >> 3) & 0x70))

// ---------------- PTX helpers ----------------
__device__ __forceinline__ uint32_t smem_u32(const void* p) {
    uint32_t a;
    asm("{ .reg .u64 t; cvta.to.shared.u64 t, %1; cvt.u32.u64 %0, t; }" : "=r"(a) : "l"(p));
    return a;
}

#define LDSM4(R, addr) \
    asm volatile("ldmatrix.sync.aligned.m8n8.x4.shared.b16 {%0,%1,%2,%3}, [%4];" \
        : "=r"((R)[0]), "=r"((R)[1]), "=r"((R)[2]), "=r"((R)[3]) : "r"(addr))

#define MMA(D, A, B0, B1) \
    asm volatile("mma.sync.aligned.m16n8k16.row.col.f32.f16.f16.f32 " \
        "{%0,%1,%2,%3}, {%4,%5,%6,%7}, {%8,%9}, {%0,%1,%2,%3};" \
        : "+f"((D)[0]), "+f"((D)[1]), "+f"((D)[2]), "+f"((D)[3]) \
        : "r"((A)[0]), "r"((A)[1]), "r"((A)[2]), "r"((A)[3]), "r"(B0), "r"(B1))

#define CP_ASYNC16(dst, src) \
    asm volatile("cp.async.cg.shared.global [%0], [%1], 16;" :: "r"(dst), "l"(src) : "memory")
#define CP_COMMIT  asm volatile("cp.async.commit_group;" ::: "memory")
#define CP_WAIT(N) asm volatile("cp.async.wait_group %0;" :: "n"(N) : "memory")

// ---------------- fp16 scratch (device globals: allocation is forbidden) ----------------
__device__ __half g_wbf[(size_t)MAXB * KDIM];
__device__ __half g_bbf[(size_t)MAXB * KDIM];
__device__ __half g_ftwbf[(size_t)HSZ * KDIM];

// ---------------- fp32 -> fp16 convert ----------------
__global__ void cvt_fp16_kernel(const float* __restrict__ src,
                                __half* __restrict__ dst, int n4) {
    int i = blockIdx.x * blockDim.x + threadIdx.x;
    if (i < n4) {
        float4 v = ((const float4*)src)[i];
        union { __half2 h2[2]; uint2 u; } pk;
        pk.h2[0] = __floats2half2_rn(v.x, v.y);
        pk.h2[1] = __floats2half2_rn(v.z, v.w);
        ((uint2*)dst)[i] = pk.u;
    }
}

// ---------------- stage loader: 3 tiles of 128 rows x 64 fp16, SW128 swizzle ----------------
__device__ __forceinline__ void load_stage(uint32_t dst, const __half* aw,
                                           const __half* ab, const __half* wt,
                                           int k0, int tid) {
    #pragma unroll
    for (int it = 0; it < 4; ++it) {
        const int ch = tid + it * NTHREADS;        // 0..1023 chunks of 16B
        const int rr = ch >> 3, cc = ch & 7;
        const uint32_t so = SW128(rr * 128 + cc * 16);
        const size_t go = (size_t)rr * KDIM + k0 + cc * 8;
        CP_ASYNC16(dst + so,          aw + go);
        CP_ASYNC16(dst + 16384 + so,  ab + go);
        CP_ASYNC16(dst + 32768 + so,  wt + go);
    }
}

// l1 partial accumulation for one column (8 outputs), vectorized l1 weights
#define ACCP(P, A1, A2) do { \
    (P)[0] = fmaf(la0.x, (A1), fmaf(lb0.x, (A2), (P)[0])); \
    (P)[1] = fmaf(la0.y, (A1), fmaf(lb0.y, (A2), (P)[1])); \
    (P)[2] = fmaf(la0.z, (A1), fmaf(lb0.z, (A2), (P)[2])); \
    (P)[3] = fmaf(la0.w, (A1), fmaf(lb0.w, (A2), (P)[3])); \
    (P)[4] = fmaf(la1.x, (A1), fmaf(lb1.x, (A2), (P)[4])); \
    (P)[5] = fmaf(la1.y, (A1), fmaf(lb1.y, (A2), (P)[5])); \
    (P)[6] = fmaf(la1.z, (A1), fmaf(lb1.z, (A2), (P)[6])); \
    (P)[7] = fmaf(la1.w, (A1), fmaf(lb1.w, (A2), (P)[7])); \
} while (0)

// ---------------- fused NNUE kernel ----------------
__global__ __launch_bounds__(NTHREADS) void nnue_main(
    const __half* __restrict__ Aw, const __half* __restrict__ Ab,
    const __half* __restrict__ Wt,
    const float* __restrict__ stm, const float* __restrict__ ft_b,
    const float* __restrict__ l1_w, const float* __restrict__ l1_b,
    const float* __restrict__ l2_w, const float* __restrict__ l2_b,
    const float* __restrict__ l3_w, const float* __restrict__ l3_b,
    float* __restrict__ out, int B, int out_size)
{
    extern __shared__ char smem[];
    const int tid = threadIdx.x;
    const int wid = tid >> 5, lid = tid & 31;
    const int wr = wid >> 1;   // 0..3 : 32-row band
    const int wc = wid & 1;    // 0..1 : 64-col band
    const uint32_t sb = smem_u32(smem);

    float* l1t   = (float*)(smem + OFF_L1T);   // [hc][i] transposed l1_w
    float* ftb_s = (float*)(smem + OFF_FTB);

    // preload l1_w transposed + ft_b (coalesced global reads)
    for (int idx = tid; idx < 2 * HSZ * 8; idx += NTHREADS) {
        const int i = idx >> 11;        // 0..7
        const int hc = idx & 2047;      // 0..2047
        l1t[hc * 8 + i] = l1_w[idx];    // idx == i*2048 + hc
    }
    for (int idx = tid; idx < HSZ; idx += NTHREADS) ftb_s[idx] = ft_b[idx];

    const int row0 = blockIdx.x * BM;

    // rows owned by this thread's accumulator fragments
    // p[k] : k = mt*2 + half, row = wr*32 + mt*16 + half*8 + lid/4
    float s_[4], iv_[4];
    #pragma unroll
    for (int k = 0; k < 4; ++k) {
        const int rl = wr * 32 + (k >> 1) * 16 + (k & 1) * 8 + (lid >> 2);
        s_[k] = stm[row0 + rl];
        iv_[k] = 1.0f - s_[k];
    }

    float p[4][8];
    #pragma unroll
    for (int k = 0; k < 4; ++k)
        #pragma unroll
        for (int i = 0; i < 8; ++i) p[k][i] = 0.0f;

    // per-lane ldmatrix geometry
    const int a_kb  = (lid >> 4) << 4;                          // A: 0 or 16 bytes
    const int a_rb  = (wr * 32 + (lid & 15)) * 128;             // A row byte base (mt0)
    const int b_row = wc * 64 + (lid & 7) + ((lid >> 4) << 3);  // B: n row
    const int b_kb  = ((lid >> 3) & 1) << 4;                    // B: 0 or 16 bytes

    const __half* Awr = Aw + (size_t)row0 * KDIM;
    const __half* Abr = Ab + (size_t)row0 * KDIM;

    __syncthreads();   // l1t/ftb ready

    // prologue for h-tile 0: stages 0 and 1
    {
        const __half* Wh = Wt;
        load_stage(sb + OFF_STG,             Awr, Abr, Wh, 0,  tid); CP_COMMIT;
        load_stage(sb + OFF_STG + STG_BYTES, Awr, Abr, Wh, KC, tid); CP_COMMIT;
    }

    for (int ht = 0; ht < NHT; ++ht) {
        float accW[64], accB[64];   // [mt*32 + nt*4 + e]
        #pragma unroll
        for (int i = 0; i < 64; ++i) { accW[i] = 0.0f; accB[i] = 0.0f; }

        const __half* Wh = Wt + (size_t)(ht * BN) * KDIM;

        int cbuf = 0;               // buffer holding chunk ks
        for (int ks = 0; ks < KSTAGES; ++ks) {
            CP_WAIT(1);             // chunk ks landed (<=1 newer group pending)
            __syncthreads();        // everyone done with buffer (ks-1)%3 -> safe to refill

            // prefetch chunk ks+2 into buffer (ks+2)%3 (the one consumed at ks-1)
            if (ks + 2 < KSTAGES) {
                int pbuf = cbuf + 2; if (pbuf >= NBUF) pbuf -= NBUF;
                load_stage(sb + OFF_STG + pbuf * STG_BYTES, Awr, Abr, Wh,
                           (ks + 2) * KC, tid);
            }
            CP_COMMIT;              // commit (possibly empty) to keep group counts aligned

            const uint32_t base = sb + OFF_STG + cbuf * STG_BYTES;
            const uint32_t awb = base, abb = base + 16384, wbb = base + 32768;

            #pragma unroll
            for (int kk = 0; kk < 4; ++kk) {
                const int kb = kk * 32;
                uint32_t aw0[4], aw1[4], ab0[4], ab1[4];
                LDSM4(aw0, awb + SW128(a_rb + kb + a_kb));
                LDSM4(aw1, awb + SW128(a_rb + 16 * 128 + kb + a_kb));
                LDSM4(ab0, abb + SW128(a_rb + kb + a_kb));
                LDSM4(ab1, abb + SW128(a_rb + 16 * 128 + kb + a_kb));
                #pragma unroll
                for (int bt = 0; bt < 4; ++bt) {
                    uint32_t bb[4];
                    LDSM4(bb, wbb + SW128((b_row + bt * 16) * 128 + kb + b_kb));
                    MMA(&accW[(bt * 2)     * 4], aw0, bb[0], bb[1]);
                    MMA(&accW[(bt * 2 + 1) * 4], aw0, bb[2], bb[3]);
                    MMA(&accW[32 + (bt * 2)     * 4], aw1, bb[0], bb[1]);
                    MMA(&accW[32 + (bt * 2 + 1) * 4], aw1, bb[2], bb[3]);
                    MMA(&accB[(bt * 2)     * 4], ab0, bb[0], bb[1]);
                    MMA(&accB[(bt * 2 + 1) * 4], ab0, bb[2], bb[3]);
                    MMA(&accB[32 + (bt * 2)     * 4], ab1, bb[0], bb[1]);
                    MMA(&accB[32 + (bt * 2 + 1) * 4], ab1, bb[2], bb[3]);
                }
            }

            if (++cbuf == NBUF) cbuf = 0;
        }

        // all warps done consuming this h-tile's stages
        __syncthreads();

        // overlap: issue next h-tile's prologue (stages 0,1 -> buffers 0,1)
        // BEFORE the FFMA epilogue, so loads fly during the epilogue.
        if (ht + 1 < NHT) {
            const __half* Wn = Wt + (size_t)((ht + 1) * BN) * KDIM;
            load_stage(sb + OFF_STG,             Awr, Abr, Wn, 0,  tid); CP_COMMIT;
            load_stage(sb + OFF_STG + STG_BYTES, Awr, Abr, Wn, KC, tid); CP_COMMIT;
        }

        // ---- epilogue: ft_b add, stm mix, clip, l1 partial accumulation ----
        #pragma unroll
        for (int mt = 0; mt < 2; ++mt) {
            const float sA = s_[mt * 2],     ivA = iv_[mt * 2];
            const float sB = s_[mt * 2 + 1], ivB = iv_[mt * 2 + 1];
            #pragma unroll
            for (int nt = 0; nt < 8; ++nt) {
                #pragma unroll
                for (int j = 0; j < 2; ++j) {
                    const int hc = ht * BN + wc * 64 + nt * 8 + (lid & 3) * 2 + j;
                    const float fb = ftb_s[hc];
                    const float wvA = accW[mt * 32 + nt * 4 + j] + fb;
                    const float bvA = accB[mt * 32 + nt * 4 + j] + fb;
                    const float wvB = accW[mt * 32 + nt * 4 + 2 + j] + fb;
                    const float bvB = accB[mt * 32 + nt * 4 + 2 + j] + fb;
                    const float a1A = __saturatef(sA * wvA + ivA * bvA);
                    const float a2A = __saturatef(sA * bvA + ivA * wvA);
                    const float a1B = __saturatef(sB * wvB + ivB * bvB);
                    const float a2B = __saturatef(sB * bvB + ivB * wvB);
                    const float4 la0 = *(const float4*)(l1t + hc * 8);
                    const float4 la1 = *(const float4*)(l1t + hc * 8 + 4);
                    const float4 lb0 = *(const float4*)(l1t + (HSZ + hc) * 8);
                    const float4 lb1 = *(const float4*)(l1t + (HSZ + hc) * 8 + 4);
                    ACCP(p[mt * 2],     a1A, a2A);
                    ACCP(p[mt * 2 + 1], a1B, a2B);
                }
            }
        }
    }

    // ---- reduce l1 partials across lane%4 quads, then across the 2 warp-cols ----
    #pragma unroll
    for (int k = 0; k < 4; ++k)
        #pragma unroll
        for (int i = 0; i < 8; ++i) {
            p[k][i] += __shfl_xor_sync(0xffffffffu, p[k][i], 1);
            p[k][i] += __shfl_xor_sync(0xffffffffu, p[k][i], 2);
        }

    CP_WAIT(0);
    __syncthreads();
    float* red = (float*)(smem + OFF_STG);   // 128 x 8 f32, reuses stage area
    if (wc == 1 && (lid & 3) == 0) {
        #pragma unroll
        for (int k = 0; k < 4; ++k) {
            const int rl = wr * 32 + (k >> 1) * 16 + (k & 1) * 8 + (lid >> 2);
            #pragma unroll
            for (int i = 0; i < 8; ++i) red[rl * 8 + i] = p[k][i];
        }
    }
    __syncthreads();
    if (wc == 0 && (lid & 3) == 0) {
        #pragma unroll
        for (int k = 0; k < 4; ++k) {
            const int rl = wr * 32 + (k >> 1) * 16 + (k & 1) * 8 + (lid >> 2);
            float x1[8];
            #pragma unroll
            for (int i = 0; i < 8; ++i)
                x1[i] = __saturatef(p[k][i] + red[rl * 8 + i] + l1_b[i]);
            float raw = l3_b[0];
            #pragma unroll
            for (int j = 0; j < 32; ++j) {
                float s2 = l2_b[j];
                #pragma unroll
                for (int i = 0; i < 8; ++i) s2 = fmaf(l2_w[j * 8 + i], x1[i], s2);
                s2 = __saturatef(s2);
                raw = fmaf(l3_w[j], s2, raw);
            }
            const int grow = row0 + rl;
            out[grow] = 1.0f / (1.0f + expf(-raw));
            if (out_size >= 2 * B) out[B + grow] = raw;
        }
    }
}

// ---------------- launch ----------------
extern "C" void kernel_launch(void* const* d_in, const int* in_sizes, int n_in,
                              void* d_out, int out_size) {
    const float* wf  = (const float*)d_in[0];
    const float* bf  = (const float*)d_in[1];
    const float* stm = (const float*)d_in[2];
    const float* ftw = (const float*)d_in[3];
    const float* ftb = (const float*)d_in[4];
    const float* l1w = (const float*)d_in[5];
    const float* l1b = (const float*)d_in[6];
    const float* l2w = (const float*)d_in[7];
    const float* l2b = (const float*)d_in[8];
    const float* l3w = (const float*)d_in[9];
    const float* l3b = (const float*)d_in[10];

    const int B = in_sizes[0] / KDIM;

    __half *pw = nullptr, *pb = nullptr, *pf = nullptr;
    cudaGetSymbolAddress((void**)&pw, g_wbf);
    cudaGetSymbolAddress((void**)&pb, g_bbf);
    cudaGetSymbolAddress((void**)&pf, g_ftwbf);

    cudaFuncSetAttribute(nnue_main, cudaFuncAttributeMaxDynamicSharedMemorySize, SMEM_TOTAL);

    const int n4 = B * KDIM / 4;
    cvt_fp16_kernel<<<(n4 + 255) / 256, 256>>>(wf, pw, n4);
    cvt_fp16_kernel<<<(n4 + 255) / 256, 256>>>(bf, pb, n4);
    const int n4w = HSZ * KDIM / 4;
    cvt_fp16_kernel<<<(n4w + 255) / 256, 256>>>(ftw, pf, n4w);

    nnue_main<<<B / BM, NTHREADS, SMEM_TOTAL>>>(pw, pb, pf, stm, ftb,
                                                l1w, l1b, l2w, l2b, l3w, l3b,
                                                (float*)d_out, B, out_size);
}